// round 14
// baseline (speedup 1.0000x reference)
#include <cuda_runtime.h>
#include <cuda_bf16.h>
#include <cstdint>

#define NN 50000
#define DD 128
#define EE 800000
#define BN_EPS 1e-5f

// ---------------- scratch (no allocs allowed) ----------------
__device__ float g_buf1[NN * DD];          // agg -> h (pre-BN)
__device__ float g_buf2[NN * DD];          // t = relu(h@W1+b1)
__device__ float g_stats[2 * DD];
__device__ float g_scale[DD];
__device__ float g_shift[DD];
__device__ int g_is64;
__device__ __nv_bfloat16 g_w1hi[DD * DD];  // W^T hi/lo splits, [n][k] bf16
__device__ __nv_bfloat16 g_w1lo[DD * DD];
__device__ __nv_bfloat16 g_w2hi[DD * DD];
__device__ __nv_bfloat16 g_w2lo[DD * DD];
// CSR scratch
__device__ int g_src[EE];
__device__ int g_dst[EE];
__device__ int g_cnt[NN];
__device__ int g_off[NN];
__device__ int g_cursor[NN];
__device__ int2 g_pair[EE];                // {edge id, src} bucketed by dst
__device__ int g_bsum[64];                 // block sums for device-wide scan

#define SCAN_BLK 1024
#define SCAN_NB ((NN + SCAN_BLK - 1) / SCAN_BLK)   // 49

// ---------------- helpers ----------------
__device__ __forceinline__ uint32_t smem_u32(const void* p) {
    uint32_t a;
    asm("{ .reg .u64 t; cvta.to.shared.u64 t, %1; cvt.u32.u64 %0, t; }" : "=r"(a) : "l"(p));
    return a;
}
#define LDSM4(r, addr)                                                        \
    asm volatile("ldmatrix.sync.aligned.m8n8.x4.shared.b16 {%0,%1,%2,%3}, [%4];" \
                 : "=r"((r)[0]), "=r"((r)[1]), "=r"((r)[2]), "=r"((r)[3])     \
                 : "r"(addr))
#define MMA(ac, a, b0, b1)                                                    \
    asm volatile(                                                             \
        "mma.sync.aligned.m16n8k16.row.col.f32.bf16.bf16.f32 "                \
        "{%0,%1,%2,%3}, {%4,%5,%6,%7}, {%8,%9}, {%0,%1,%2,%3};"               \
        : "+f"((ac)[0]), "+f"((ac)[1]), "+f"((ac)[2]), "+f"((ac)[3])          \
        : "r"((a)[0]), "r"((a)[1]), "r"((a)[2]), "r"((a)[3]), "r"(b0), "r"(b1))

// ---------------- zero counters + stats + dtype probe ----------------
__global__ void zero_kernel(const int* __restrict__ ei32) {
    int i = blockIdx.x * blockDim.x + threadIdx.x;
    if (i < NN) g_cnt[i] = 0;
    if (i < 2 * DD) g_stats[i] = 0.f;
    if (blockIdx.x == 0 && threadIdx.x == 0) {
        int zeros = 0;
        for (int k = 1; k < 256; k += 2) zeros += (ei32[k] == 0);
        g_is64 = (zeros >= 96) ? 1 : 0;
    }
}

// ---------------- prep: W -> transposed bf16 hi/lo splits [n][k] ----------------
__global__ void prep_w(const float* __restrict__ W1, const float* __restrict__ W2) {
    const float* W = blockIdx.y ? W2 : W1;
    __nv_bfloat16* hi = blockIdx.y ? g_w2hi : g_w1hi;
    __nv_bfloat16* lo = blockIdx.y ? g_w2lo : g_w1lo;
    int k = blockIdx.x, n = threadIdx.x;
    float v = W[k * DD + n];
    __nv_bfloat16 h = __float2bfloat16(v);
    hi[n * DD + k] = h;
    lo[n * DD + k] = __float2bfloat16(v - __bfloat162float(h));
}

// ---------------- convert: edge_index -> int32 + dst histogram ----------------
__global__ void convert_kernel(const void* __restrict__ ei) {
    int e = blockIdx.x * blockDim.x + threadIdx.x;
    if (e >= EE) return;
    long long s, d;
    if (g_is64) {
        const long long* p = (const long long*)ei;
        s = p[e];
        d = p[EE + e];
    } else {
        const int* p = (const int*)ei;
        s = p[e];
        d = p[EE + e];
    }
    int si = (int)s, di = (int)d;
    if ((unsigned)si >= NN) si = 0;
    if ((unsigned)di >= NN) di = 0;
    g_src[e] = si;
    g_dst[e] = di;
    atomicAdd(&g_cnt[di], 1);
}

// ---------------- device-wide exclusive scan, 3 phases ----------------
__global__ void scanA_kernel() {
    __shared__ int warp_sums[32];
    int tid = threadIdx.x;
    int i = blockIdx.x * SCAN_BLK + tid;
    int v = (i < NN) ? g_cnt[i] : 0;
    int incl = v;
#pragma unroll
    for (int d = 1; d < 32; d <<= 1) {
        int t = __shfl_up_sync(0xFFFFFFFFu, incl, d);
        if ((tid & 31) >= d) incl += t;
    }
    if ((tid & 31) == 31) warp_sums[tid >> 5] = incl;
    __syncthreads();
    if (tid < 32) {
        int w = warp_sums[tid];
        int ws = w;
#pragma unroll
        for (int d = 1; d < 32; d <<= 1) {
            int t = __shfl_up_sync(0xFFFFFFFFu, ws, d);
            if (tid >= d) ws += t;
        }
        warp_sums[tid] = ws - w;  // exclusive warp offset
        if (tid == 31) g_bsum[blockIdx.x] = ws;  // block total
    }
    __syncthreads();
    int excl = incl - v + warp_sums[tid >> 5];
    if (i < NN) g_off[i] = excl;
}

__global__ void scanB_kernel() {
    __shared__ int w0tot;
    int tid = threadIdx.x;  // 64 threads
    int v = (tid < SCAN_NB) ? g_bsum[tid] : 0;
    int incl = v;
#pragma unroll
    for (int d = 1; d < 32; d <<= 1) {
        int t = __shfl_up_sync(0xFFFFFFFFu, incl, d);
        if ((tid & 31) >= d) incl += t;
    }
    if (tid == 31) w0tot = incl;
    __syncthreads();
    int excl = incl - v + ((tid >= 32) ? w0tot : 0);
    if (tid < SCAN_NB) g_bsum[tid] = excl;
}

__global__ void scanC_kernel() {
    int tid = threadIdx.x;
    int i = blockIdx.x * SCAN_BLK + tid;
    if (i >= NN) return;
    int o = g_off[i] + g_bsum[blockIdx.x];
    g_off[i] = o;
    g_cursor[i] = o;
}

// ---------------- scatter: bucket {edge, src} pairs by dst ----------------
__global__ void scatter_kernel() {
    int e = blockIdx.x * blockDim.x + threadIdx.x;
    if (e >= EE) return;
    int d = g_dst[e];
    int pos = atomicAdd(&g_cursor[d], 1);
    g_pair[pos] = make_int2(e, g_src[e]);
}

// ---------------- aggregate: warp/node, cp.async 8-deep ea ring (race-free) ------
// Ring discipline: wait -> consume slot -> refill freed slot -> commit.
// Group math: prologue commits AD groups; before consuming edge i, commits = AD+i;
// wait_group(AD-1) => completed >= i+1 => edge i's group done.
#define AD 8
__global__ void agg_kernel(const float* __restrict__ x,
                           const float* __restrict__ ea) {
    __shared__ __align__(16) float4 sea[8][AD][32];  // [warp][slot][lane] = 32KB
    int wb = threadIdx.x >> 5;
    int ln = threadIdx.x & 31;
    int w = (blockIdx.x * blockDim.x + threadIdx.x) >> 5;
    if (w >= NN) return;
    int beg = g_off[w];
    int cnt = g_cnt[w];
    int c = ln * 4;
    float4 acc = __ldg((const float4*)(x + (size_t)w * DD + c));  // h = x + agg
    const int2* pp = g_pair + beg;
    const uint32_t sslot0 = smem_u32(&sea[wb][0][ln]);  // + slot*512 bytes

    // prologue: edges 0..AD-1 into slots 0..AD-1; exactly AD commits
#pragma unroll
    for (int j = 0; j < AD; j++) {
        if (j < cnt) {
            int2 p = __ldg(pp + j);
            const float* gp = ea + (size_t)p.x * DD + c;
            asm volatile("cp.async.cg.shared.global [%0], [%1], 16;"
                         :: "r"(sslot0 + j * 512u), "l"(gp) : "memory");
        }
        asm volatile("cp.async.commit_group;" ::: "memory");
    }

    for (int i = 0; i < cnt; i++) {
        asm volatile("cp.async.wait_group %0;" :: "n"(AD - 1) : "memory");
        // consume edge i from its slot (now guaranteed complete)
        int2 pc = __ldg(pp + i);  // L1 hit (address touched at issue time)
        float4 b = __ldg((const float4*)(x + (size_t)pc.y * DD + c));
        float4 a = *(const float4*)((const char*)&sea[wb][0][ln] + ((i & (AD - 1)) * 512u));
        acc.x += fmaxf(a.x + b.x, 0.f);
        acc.y += fmaxf(a.y + b.y, 0.f);
        acc.z += fmaxf(a.z + b.z, 0.f);
        acc.w += fmaxf(a.w + b.w, 0.f);
        // refill the freed slot with edge i+AD, then commit (1 per iteration)
        if (i + AD < cnt) {
            int2 p = __ldg(pp + i + AD);
            const float* gp = ea + (size_t)p.x * DD + c;
            asm volatile("cp.async.cg.shared.global [%0], [%1], 16;"
                         :: "r"(sslot0 + ((i & (AD - 1)) * 512u)), "l"(gp) : "memory");
        }
        asm volatile("cp.async.commit_group;" ::: "memory");
    }
    *(float4*)(g_buf1 + (size_t)w * DD + c) = acc;
}

// ---------------- HMMA GEMM: 64x128 out tile per CTA, 2 CTAs/SM ----------------
#define AST 136
#define OF_AHI 1024u
#define OF_ALO (1024u + 17408u)
#define OF_BHI (1024u + 2u * 17408u)
#define OF_BLO (1024u + 2u * 17408u + 34816u)
#define MM_SMEM (1024 + 2 * 17408 + 2 * 34816)

template <int MODE>
__global__ void __launch_bounds__(256, 2) mm_kernel(const float* __restrict__ bias,
                                                    const float* __restrict__ resid) {
    extern __shared__ char smem[];
    const uint32_t sb = smem_u32(smem);
    float* sbias = (float*)smem;
    const int tid = threadIdx.x, wid = tid >> 5, ln = tid & 31;
    const int row0 = blockIdx.x * 64;

    const float* A = MODE ? g_buf2 : g_buf1;
    float* out = MODE ? g_buf1 : g_buf2;
    const __nv_bfloat16* Bhi = MODE ? g_w2hi : g_w1hi;
    const __nv_bfloat16* Blo = MODE ? g_w2lo : g_w1lo;

    if (tid < 128) sbias[tid] = bias[tid];

    {
        __nv_bfloat16* sAh = (__nv_bfloat16*)(smem + OF_AHI);
        __nv_bfloat16* sAl = (__nv_bfloat16*)(smem + OF_ALO);
#pragma unroll
        for (int rr = 0; rr < 8; rr++) {
            int r = wid * 8 + rr;
            int gr = row0 + r;
            float4 v = make_float4(0.f, 0.f, 0.f, 0.f);
            if (gr < NN) v = *(const float4*)(A + (size_t)gr * DD + ln * 4);
            __nv_bfloat16 hx = __float2bfloat16(v.x), hy = __float2bfloat16(v.y);
            __nv_bfloat16 hz = __float2bfloat16(v.z), hw = __float2bfloat16(v.w);
            __nv_bfloat162 hi0 = __halves2bfloat162(hx, hy);
            __nv_bfloat162 hi1 = __halves2bfloat162(hz, hw);
            __nv_bfloat162 lo0 = __halves2bfloat162(
                __float2bfloat16(v.x - __bfloat162float(hx)),
                __float2bfloat16(v.y - __bfloat162float(hy)));
            __nv_bfloat162 lo1 = __halves2bfloat162(
                __float2bfloat16(v.z - __bfloat162float(hz)),
                __float2bfloat16(v.w - __bfloat162float(hw)));
            int o = r * AST + ln * 4;
            *(__nv_bfloat162*)(sAh + o) = hi0;
            *(__nv_bfloat162*)(sAh + o + 2) = hi1;
            *(__nv_bfloat162*)(sAl + o) = lo0;
            *(__nv_bfloat162*)(sAl + o + 2) = lo1;
        }
    }
    {
        __nv_bfloat16* sBh = (__nv_bfloat16*)(smem + OF_BHI);
        __nv_bfloat16* sBl = (__nv_bfloat16*)(smem + OF_BLO);
#pragma unroll
        for (int rr = 0; rr < 16; rr++) {
            int n = wid * 16 + rr;
            uint2 vh = *(const uint2*)(Bhi + (size_t)n * DD + ln * 4);
            uint2 vl = *(const uint2*)(Blo + (size_t)n * DD + ln * 4);
            int o = n * AST + ln * 4;
            *(uint32_t*)((char*)sBh + (size_t)o * 2) = vh.x;
            *(uint32_t*)((char*)sBh + (size_t)o * 2 + 4) = vh.y;
            *(uint32_t*)((char*)sBl + (size_t)o * 2) = vl.x;
            *(uint32_t*)((char*)sBl + (size_t)o * 2 + 4) = vl.y;
        }
    }
    __syncthreads();

    const int m0 = (wid & 3) * 16;
    const int cb = (wid >> 2) * 64;
    const uint32_t a_off =
        (uint32_t)((m0 + ((ln >> 3) & 1) * 8 + (ln & 7)) * AST + ((ln >> 4) & 1) * 8) * 2u;
    const uint32_t b_off =
        (uint32_t)((cb + ((ln >> 4) & 1) * 8 + (ln & 7)) * AST + ((ln >> 3) & 1) * 8) * 2u;
    const uint32_t aAh = sb + OF_AHI + a_off, aAl = sb + OF_ALO + a_off;
    const uint32_t aBh = sb + OF_BHI + b_off, aBl = sb + OF_BLO + b_off;

    float acc[8][4];
#pragma unroll
    for (int f = 0; f < 8; f++)
#pragma unroll
        for (int j = 0; j < 4; j++) acc[f][j] = 0.f;

#pragma unroll
    for (int ks = 0; ks < 8; ks++) {
        const uint32_t kb = ks * 32u;
        uint32_t ah[4], al[4];
        LDSM4(ah, aAh + kb);
        LDSM4(al, aAl + kb);
#pragma unroll
        for (int nb = 0; nb < 4; nb++) {
            uint32_t bh[4], bl[4];
            const uint32_t bo = (uint32_t)(nb * 16 * AST) * 2u + kb;
            LDSM4(bh, aBh + bo);
            LDSM4(bl, aBl + bo);
            MMA(acc[2 * nb], ah, bh[0], bh[1]);
            MMA(acc[2 * nb + 1], ah, bh[2], bh[3]);
            MMA(acc[2 * nb], ah, bl[0], bl[1]);
            MMA(acc[2 * nb + 1], ah, bl[2], bl[3]);
            MMA(acc[2 * nb], al, bh[0], bh[1]);
            MMA(acc[2 * nb + 1], al, bh[2], bh[3]);
        }
    }

    const int gr0 = row0 + m0 + (ln >> 2);
    const int gr1 = gr0 + 8;
#pragma unroll
    for (int f = 0; f < 8; f++) {
        const int c = cb + f * 8 + (ln & 3) * 2;
        float2 v0 = make_float2(acc[f][0] + sbias[c], acc[f][1] + sbias[c + 1]);
        float2 v1 = make_float2(acc[f][2] + sbias[c], acc[f][3] + sbias[c + 1]);
        if (MODE == 0) {
            v0.x = fmaxf(v0.x, 0.f); v0.y = fmaxf(v0.y, 0.f);
            v1.x = fmaxf(v1.x, 0.f); v1.y = fmaxf(v1.y, 0.f);
            if (gr0 < NN) *(float2*)(out + (size_t)gr0 * DD + c) = v0;
            if (gr1 < NN) *(float2*)(out + (size_t)gr1 * DD + c) = v1;
        } else {
            if (gr0 < NN) {
                float2 r = *(const float2*)(resid + (size_t)gr0 * DD + c);
                v0.x += r.x; v0.y += r.y;
                *(float2*)(out + (size_t)gr0 * DD + c) = v0;
            }
            if (gr1 < NN) {
                float2 r = *(const float2*)(resid + (size_t)gr1 * DD + c);
                v1.x += r.x; v1.y += r.y;
                *(float2*)(out + (size_t)gr1 * DD + c) = v1;
            }
        }
    }
}

// ---------------- BN stats over g_buf1 ----------------
__global__ void stats_kernel() {
    __shared__ float s[2 * DD];
    int tid = threadIdx.x;
    if (tid < 2 * DD) s[tid] = 0.f;
    __syncthreads();
    float cs[4] = {0.f, 0.f, 0.f, 0.f}, cq[4] = {0.f, 0.f, 0.f, 0.f};
    int stride = gridDim.x * blockDim.x;
    for (int i = blockIdx.x * blockDim.x + tid; i < NN * DD / 4; i += stride) {
        float4 v = ((const float4*)g_buf1)[i];
        cs[0] += v.x; cq[0] += v.x * v.x;
        cs[1] += v.y; cq[1] += v.y * v.y;
        cs[2] += v.z; cq[2] += v.z * v.z;
        cs[3] += v.w; cq[3] += v.w * v.w;
    }
    int c4 = (tid & 31) * 4;
#pragma unroll
    for (int j = 0; j < 4; j++) {
        atomicAdd(&s[c4 + j], cs[j]);
        atomicAdd(&s[DD + c4 + j], cq[j]);
    }
    __syncthreads();
    if (tid < 2 * DD) atomicAdd(&g_stats[tid], s[tid]);
}

// ---------------- finalize + normalize ----------------
__global__ void finalize_kernel(const float* __restrict__ gamma,
                                const float* __restrict__ beta) {
    int c = threadIdx.x;
    float mean = g_stats[c] * (1.0f / NN);
    float var = g_stats[DD + c] * (1.0f / NN) - mean * mean;
    float sc = rsqrtf(var + BN_EPS) * gamma[c];
    g_scale[c] = sc;
    g_shift[c] = beta[c] - mean * sc;
}

__global__ void norm_kernel(float* __restrict__ out) {
    int i = blockIdx.x * blockDim.x + threadIdx.x;
    if (i >= NN * DD / 4) return;
    float4 v = ((const float4*)g_buf1)[i];
    float4 sc = ((const float4*)g_scale)[i & 31];
    float4 sh = ((const float4*)g_shift)[i & 31];
    v.x = v.x * sc.x + sh.x;
    v.y = v.y * sc.y + sh.y;
    v.z = v.z * sc.z + sh.z;
    v.w = v.w * sc.w + sh.w;
    ((float4*)out)[i] = v;
}

extern "C" void kernel_launch(void* const* d_in, const int* in_sizes, int n_in,
                              void* d_out, int out_size) {
    const float* x = (const float*)d_in[0];
    const void* ei = d_in[1];
    const float* ea = (const float*)d_in[2];
    const float* W1 = (const float*)d_in[3];
    const float* b1 = (const float*)d_in[4];
    const float* W2 = (const float*)d_in[5];
    const float* b2 = (const float*)d_in[6];
    const float* gamma = (const float*)d_in[7];
    const float* beta = (const float*)d_in[8];
    float* out = (float*)d_out;

    cudaFuncSetAttribute(mm_kernel<0>, cudaFuncAttributeMaxDynamicSharedMemorySize, MM_SMEM);
    cudaFuncSetAttribute(mm_kernel<1>, cudaFuncAttributeMaxDynamicSharedMemorySize, MM_SMEM);

    zero_kernel<<<(NN + 255) / 256, 256>>>((const int*)ei);
    prep_w<<<dim3(DD, 2), DD>>>(W1, W2);
    convert_kernel<<<(EE + 255) / 256, 256>>>(ei);
    scanA_kernel<<<SCAN_NB, SCAN_BLK>>>();
    scanB_kernel<<<1, 64>>>();
    scanC_kernel<<<SCAN_NB, SCAN_BLK>>>();
    scatter_kernel<<<(EE + 255) / 256, 256>>>();
    agg_kernel<<<(NN * 32 + 255) / 256, 256>>>(x, ea);
    mm_kernel<0><<<(NN + 63) / 64, 256, MM_SMEM>>>(b1, x);
    mm_kernel<1><<<(NN + 63) / 64, 256, MM_SMEM>>>(b2, x);
    stats_kernel<<<592, 256>>>();
    finalize_kernel<<<1, DD>>>(gamma, beta);
    norm_kernel<<<(NN * DD / 4 + 255) / 256, 256>>>(out);
}

// round 15
// speedup vs baseline: 1.1253x; 1.1253x over previous
#include <cuda_runtime.h>
#include <cuda_bf16.h>
#include <cstdint>

#define NN 50000
#define DD 128
#define EE 800000
#define BN_EPS 1e-5f

// ---------------- scratch (no allocs allowed) ----------------
__device__ float g_buf1[NN * DD];          // agg -> h (pre-BN)
__device__ float g_buf2[NN * DD];          // t = relu(h@W1+b1)
__device__ float g_stats[2 * DD];
__device__ float g_scale[DD];
__device__ float g_shift[DD];
__device__ int g_is64;
__device__ __nv_bfloat16 g_w1hi[DD * DD];  // W^T hi/lo splits, [n][k] bf16
__device__ __nv_bfloat16 g_w1lo[DD * DD];
__device__ __nv_bfloat16 g_w2hi[DD * DD];
__device__ __nv_bfloat16 g_w2lo[DD * DD];
// CSR scratch
__device__ int g_src[EE];
__device__ int g_dst[EE];
__device__ int g_cnt[NN];
__device__ int g_off[NN];
__device__ int g_cursor[NN];
__device__ int2 g_pair[EE];                // {edge id, src} bucketed by dst
__device__ int g_bsum[64];                 // block sums for device-wide scan

#define SCAN_BLK 1024
#define SCAN_NB ((NN + SCAN_BLK - 1) / SCAN_BLK)   // 49

// ---------------- helpers ----------------
__device__ __forceinline__ uint32_t smem_u32(const void* p) {
    uint32_t a;
    asm("{ .reg .u64 t; cvta.to.shared.u64 t, %1; cvt.u32.u64 %0, t; }" : "=r"(a) : "l"(p));
    return a;
}
#define LDSM4(r, addr)                                                        \
    asm volatile("ldmatrix.sync.aligned.m8n8.x4.shared.b16 {%0,%1,%2,%3}, [%4];" \
                 : "=r"((r)[0]), "=r"((r)[1]), "=r"((r)[2]), "=r"((r)[3])     \
                 : "r"(addr))
#define MMA(ac, a, b0, b1)                                                    \
    asm volatile(                                                             \
        "mma.sync.aligned.m16n8k16.row.col.f32.bf16.bf16.f32 "                \
        "{%0,%1,%2,%3}, {%4,%5,%6,%7}, {%8,%9}, {%0,%1,%2,%3};"               \
        : "+f"((ac)[0]), "+f"((ac)[1]), "+f"((ac)[2]), "+f"((ac)[3])          \
        : "r"((a)[0]), "r"((a)[1]), "r"((a)[2]), "r"((a)[3]), "r"(b0), "r"(b1))

// ---------------- zero counters + stats + dtype probe ----------------
__global__ void zero_kernel(const int* __restrict__ ei32) {
    int i = blockIdx.x * blockDim.x + threadIdx.x;
    if (i < NN) g_cnt[i] = 0;
    if (i < 2 * DD) g_stats[i] = 0.f;
    if (blockIdx.x == 0 && threadIdx.x == 0) {
        int zeros = 0;
        for (int k = 1; k < 256; k += 2) zeros += (ei32[k] == 0);
        g_is64 = (zeros >= 96) ? 1 : 0;
    }
}

// ---------------- prep: W -> transposed bf16 hi/lo splits [n][k] ----------------
__global__ void prep_w(const float* __restrict__ W1, const float* __restrict__ W2) {
    const float* W = blockIdx.y ? W2 : W1;
    __nv_bfloat16* hi = blockIdx.y ? g_w2hi : g_w1hi;
    __nv_bfloat16* lo = blockIdx.y ? g_w2lo : g_w1lo;
    int k = blockIdx.x, n = threadIdx.x;
    float v = W[k * DD + n];
    __nv_bfloat16 h = __float2bfloat16(v);
    hi[n * DD + k] = h;
    lo[n * DD + k] = __float2bfloat16(v - __bfloat162float(h));
}

// ---------------- convert: edge_index -> int32 + dst histogram ----------------
__global__ void convert_kernel(const void* __restrict__ ei) {
    int e = blockIdx.x * blockDim.x + threadIdx.x;
    if (e >= EE) return;
    long long s, d;
    if (g_is64) {
        const long long* p = (const long long*)ei;
        s = p[e];
        d = p[EE + e];
    } else {
        const int* p = (const int*)ei;
        s = p[e];
        d = p[EE + e];
    }
    int si = (int)s, di = (int)d;
    if ((unsigned)si >= NN) si = 0;
    if ((unsigned)di >= NN) di = 0;
    g_src[e] = si;
    g_dst[e] = di;
    atomicAdd(&g_cnt[di], 1);
}

// ---------------- device-wide exclusive scan, 3 phases ----------------
__global__ void scanA_kernel() {
    __shared__ int warp_sums[32];
    int tid = threadIdx.x;
    int i = blockIdx.x * SCAN_BLK + tid;
    int v = (i < NN) ? g_cnt[i] : 0;
    int incl = v;
#pragma unroll
    for (int d = 1; d < 32; d <<= 1) {
        int t = __shfl_up_sync(0xFFFFFFFFu, incl, d);
        if ((tid & 31) >= d) incl += t;
    }
    if ((tid & 31) == 31) warp_sums[tid >> 5] = incl;
    __syncthreads();
    if (tid < 32) {
        int w = warp_sums[tid];
        int ws = w;
#pragma unroll
        for (int d = 1; d < 32; d <<= 1) {
            int t = __shfl_up_sync(0xFFFFFFFFu, ws, d);
            if (tid >= d) ws += t;
        }
        warp_sums[tid] = ws - w;  // exclusive warp offset
        if (tid == 31) g_bsum[blockIdx.x] = ws;  // block total
    }
    __syncthreads();
    int excl = incl - v + warp_sums[tid >> 5];
    if (i < NN) g_off[i] = excl;
}

__global__ void scanB_kernel() {
    __shared__ int w0tot;
    int tid = threadIdx.x;  // 64 threads
    int v = (tid < SCAN_NB) ? g_bsum[tid] : 0;
    int incl = v;
#pragma unroll
    for (int d = 1; d < 32; d <<= 1) {
        int t = __shfl_up_sync(0xFFFFFFFFu, incl, d);
        if ((tid & 31) >= d) incl += t;
    }
    if (tid == 31) w0tot = incl;
    __syncthreads();
    int excl = incl - v + ((tid >= 32) ? w0tot : 0);
    if (tid < SCAN_NB) g_bsum[tid] = excl;
}

__global__ void scanC_kernel() {
    int tid = threadIdx.x;
    int i = blockIdx.x * SCAN_BLK + tid;
    if (i >= NN) return;
    int o = g_off[i] + g_bsum[blockIdx.x];
    g_off[i] = o;
    g_cursor[i] = o;
}

// ---------------- scatter: bucket {edge, src} pairs by dst ----------------
__global__ void scatter_kernel() {
    int e = blockIdx.x * blockDim.x + threadIdx.x;
    if (e >= EE) return;
    int d = g_dst[e];
    int pos = atomicAdd(&g_cursor[d], 1);
    g_pair[pos] = make_int2(e, g_src[e]);
}

// ---------------- aggregate: warp per node, unroll-4 pipelined gather ----------------
__global__ void agg_kernel(const float* __restrict__ x,
                           const float* __restrict__ ea) {
    int w = (blockIdx.x * blockDim.x + threadIdx.x) >> 5;
    int ln = threadIdx.x & 31;
    if (w >= NN) return;
    int beg = g_off[w];
    int cnt = g_cnt[w];
    int c = ln * 4;
    float4 acc = __ldg((const float4*)(x + (size_t)w * DD + c));  // h = x + agg
    const int2* pp = g_pair + beg;

    int i = 0;
    if (cnt >= 8) {
        int2 p0 = __ldg(pp + 0), p1 = __ldg(pp + 1);
        int2 p2 = __ldg(pp + 2), p3 = __ldg(pp + 3);
        for (; i + 7 < cnt; i += 4) {
            int2 n0 = __ldg(pp + i + 4), n1 = __ldg(pp + i + 5);
            int2 n2 = __ldg(pp + i + 6), n3 = __ldg(pp + i + 7);
            float4 a0 = __ldcs((const float4*)(ea + (size_t)p0.x * DD + c));
            float4 b0 = __ldg((const float4*)(x + (size_t)p0.y * DD + c));
            float4 a1 = __ldcs((const float4*)(ea + (size_t)p1.x * DD + c));
            float4 b1 = __ldg((const float4*)(x + (size_t)p1.y * DD + c));
            float4 a2 = __ldcs((const float4*)(ea + (size_t)p2.x * DD + c));
            float4 b2 = __ldg((const float4*)(x + (size_t)p2.y * DD + c));
            float4 a3 = __ldcs((const float4*)(ea + (size_t)p3.x * DD + c));
            float4 b3 = __ldg((const float4*)(x + (size_t)p3.y * DD + c));
            acc.x += fmaxf(a0.x + b0.x, 0.f) + fmaxf(a1.x + b1.x, 0.f);
            acc.y += fmaxf(a0.y + b0.y, 0.f) + fmaxf(a1.y + b1.y, 0.f);
            acc.z += fmaxf(a0.z + b0.z, 0.f) + fmaxf(a1.z + b1.z, 0.f);
            acc.w += fmaxf(a0.w + b0.w, 0.f) + fmaxf(a1.w + b1.w, 0.f);
            acc.x += fmaxf(a2.x + b2.x, 0.f) + fmaxf(a3.x + b3.x, 0.f);
            acc.y += fmaxf(a2.y + b2.y, 0.f) + fmaxf(a3.y + b3.y, 0.f);
            acc.z += fmaxf(a2.z + b2.z, 0.f) + fmaxf(a3.z + b3.z, 0.f);
            acc.w += fmaxf(a2.w + b2.w, 0.f) + fmaxf(a3.w + b3.w, 0.f);
            p0 = n0; p1 = n1; p2 = n2; p3 = n3;
        }
    }
    for (; i < cnt; i++) {
        int2 p = __ldg(pp + i);
        float4 a = __ldcs((const float4*)(ea + (size_t)p.x * DD + c));
        float4 b = __ldg((const float4*)(x + (size_t)p.y * DD + c));
        acc.x += fmaxf(a.x + b.x, 0.f);
        acc.y += fmaxf(a.y + b.y, 0.f);
        acc.z += fmaxf(a.z + b.z, 0.f);
        acc.w += fmaxf(a.w + b.w, 0.f);
    }
    *(float4*)(g_buf1 + (size_t)w * DD + c) = acc;
}

// ---------------- HMMA GEMM: 64x128 out tile per CTA, 2 CTAs/SM ----------------
// MODE 1 fuses BN column-stat accumulation (conflict-free: shfl butterfly +
// per-warp exclusive smem + one global atomic per thread).
#define AST 136
#define OF_AHI 1024u
#define OF_ALO (1024u + 17408u)
#define OF_BHI (1024u + 2u * 17408u)
#define OF_BLO (1024u + 2u * 17408u + 34816u)
#define MM_SMEM (1024 + 2 * 17408 + 2 * 34816)

template <int MODE>
__global__ void __launch_bounds__(256, 2) mm_kernel(const float* __restrict__ bias,
                                                    const float* __restrict__ resid) {
    extern __shared__ char smem[];
    const uint32_t sb = smem_u32(smem);
    float* sbias = (float*)smem;
    const int tid = threadIdx.x, wid = tid >> 5, ln = tid & 31;
    const int row0 = blockIdx.x * 64;

    const float* A = MODE ? g_buf2 : g_buf1;
    float* out = MODE ? g_buf1 : g_buf2;
    const __nv_bfloat16* Bhi = MODE ? g_w2hi : g_w1hi;
    const __nv_bfloat16* Blo = MODE ? g_w2lo : g_w1lo;

    if (tid < 128) sbias[tid] = bias[tid];

    {
        __nv_bfloat16* sAh = (__nv_bfloat16*)(smem + OF_AHI);
        __nv_bfloat16* sAl = (__nv_bfloat16*)(smem + OF_ALO);
#pragma unroll
        for (int rr = 0; rr < 8; rr++) {
            int r = wid * 8 + rr;
            int gr = row0 + r;
            float4 v = make_float4(0.f, 0.f, 0.f, 0.f);
            if (gr < NN) v = *(const float4*)(A + (size_t)gr * DD + ln * 4);
            __nv_bfloat16 hx = __float2bfloat16(v.x), hy = __float2bfloat16(v.y);
            __nv_bfloat16 hz = __float2bfloat16(v.z), hw = __float2bfloat16(v.w);
            __nv_bfloat162 hi0 = __halves2bfloat162(hx, hy);
            __nv_bfloat162 hi1 = __halves2bfloat162(hz, hw);
            __nv_bfloat162 lo0 = __halves2bfloat162(
                __float2bfloat16(v.x - __bfloat162float(hx)),
                __float2bfloat16(v.y - __bfloat162float(hy)));
            __nv_bfloat162 lo1 = __halves2bfloat162(
                __float2bfloat16(v.z - __bfloat162float(hz)),
                __float2bfloat16(v.w - __bfloat162float(hw)));
            int o = r * AST + ln * 4;
            *(__nv_bfloat162*)(sAh + o) = hi0;
            *(__nv_bfloat162*)(sAh + o + 2) = hi1;
            *(__nv_bfloat162*)(sAl + o) = lo0;
            *(__nv_bfloat162*)(sAl + o + 2) = lo1;
        }
    }
    {
        __nv_bfloat16* sBh = (__nv_bfloat16*)(smem + OF_BHI);
        __nv_bfloat16* sBl = (__nv_bfloat16*)(smem + OF_BLO);
#pragma unroll
        for (int rr = 0; rr < 16; rr++) {
            int n = wid * 16 + rr;
            uint2 vh = *(const uint2*)(Bhi + (size_t)n * DD + ln * 4);
            uint2 vl = *(const uint2*)(Blo + (size_t)n * DD + ln * 4);
            int o = n * AST + ln * 4;
            *(uint32_t*)((char*)sBh + (size_t)o * 2) = vh.x;
            *(uint32_t*)((char*)sBh + (size_t)o * 2 + 4) = vh.y;
            *(uint32_t*)((char*)sBl + (size_t)o * 2) = vl.x;
            *(uint32_t*)((char*)sBl + (size_t)o * 2 + 4) = vl.y;
        }
    }
    __syncthreads();

    const int m0 = (wid & 3) * 16;
    const int cb = (wid >> 2) * 64;
    const uint32_t a_off =
        (uint32_t)((m0 + ((ln >> 3) & 1) * 8 + (ln & 7)) * AST + ((ln >> 4) & 1) * 8) * 2u;
    const uint32_t b_off =
        (uint32_t)((cb + ((ln >> 4) & 1) * 8 + (ln & 7)) * AST + ((ln >> 3) & 1) * 8) * 2u;
    const uint32_t aAh = sb + OF_AHI + a_off, aAl = sb + OF_ALO + a_off;
    const uint32_t aBh = sb + OF_BHI + b_off, aBl = sb + OF_BLO + b_off;

    float acc[8][4];
#pragma unroll
    for (int f = 0; f < 8; f++)
#pragma unroll
        for (int j = 0; j < 4; j++) acc[f][j] = 0.f;

#pragma unroll
    for (int ks = 0; ks < 8; ks++) {
        const uint32_t kb = ks * 32u;
        uint32_t ah[4], al[4];
        LDSM4(ah, aAh + kb);
        LDSM4(al, aAl + kb);
#pragma unroll
        for (int nb = 0; nb < 4; nb++) {
            uint32_t bh[4], bl[4];
            const uint32_t bo = (uint32_t)(nb * 16 * AST) * 2u + kb;
            LDSM4(bh, aBh + bo);
            LDSM4(bl, aBl + bo);
            MMA(acc[2 * nb], ah, bh[0], bh[1]);
            MMA(acc[2 * nb + 1], ah, bh[2], bh[3]);
            MMA(acc[2 * nb], ah, bl[0], bl[1]);
            MMA(acc[2 * nb + 1], ah, bl[2], bl[3]);
            MMA(acc[2 * nb], al, bh[0], bh[1]);
            MMA(acc[2 * nb + 1], al, bh[2], bh[3]);
        }
    }

    // MODE 1: reuse A-tile smem for per-warp stats partials [8][256]
    float* sstat = (float*)(smem + OF_AHI);
    if (MODE == 1) {
        __syncthreads();  // all warps done reading tile smem
#pragma unroll
        for (int z = tid; z < 2048; z += 256) sstat[z] = 0.f;
        __syncthreads();
    }

    float st[8][4];  // per f: {sum.x, sum.y, sq.x, sq.y} (MODE 1 only)
    const int gr0 = row0 + m0 + (ln >> 2);
    const int gr1 = gr0 + 8;
#pragma unroll
    for (int f = 0; f < 8; f++) {
        const int c = cb + f * 8 + (ln & 3) * 2;
        float2 v0 = make_float2(acc[f][0] + sbias[c], acc[f][1] + sbias[c + 1]);
        float2 v1 = make_float2(acc[f][2] + sbias[c], acc[f][3] + sbias[c + 1]);
        if (MODE == 0) {
            v0.x = fmaxf(v0.x, 0.f); v0.y = fmaxf(v0.y, 0.f);
            v1.x = fmaxf(v1.x, 0.f); v1.y = fmaxf(v1.y, 0.f);
            if (gr0 < NN) *(float2*)(out + (size_t)gr0 * DD + c) = v0;
            if (gr1 < NN) *(float2*)(out + (size_t)gr1 * DD + c) = v1;
        } else {
            bool ok0 = gr0 < NN, ok1 = gr1 < NN;
            if (ok0) {
                float2 r = *(const float2*)(resid + (size_t)gr0 * DD + c);
                v0.x += r.x; v0.y += r.y;
                *(float2*)(out + (size_t)gr0 * DD + c) = v0;
            }
            if (ok1) {
                float2 r = *(const float2*)(resid + (size_t)gr1 * DD + c);
                v1.x += r.x; v1.y += r.y;
                *(float2*)(out + (size_t)gr1 * DD + c) = v1;
            }
            float x0 = ok0 ? v0.x : 0.f, y0 = ok0 ? v0.y : 0.f;
            float x1 = ok1 ? v1.x : 0.f, y1 = ok1 ? v1.y : 0.f;
            st[f][0] = x0 + x1;
            st[f][1] = y0 + y1;
            st[f][2] = x0 * x0 + x1 * x1;
            st[f][3] = y0 * y0 + y1 * y1;
        }
    }

    if (MODE == 1) {
        // butterfly-reduce over the 8 lanes sharing each column (ln^4, ln^8, ln^16)
#pragma unroll
        for (int f = 0; f < 8; f++)
#pragma unroll
            for (int j = 0; j < 4; j++) {
                float v = st[f][j];
                v += __shfl_xor_sync(0xFFFFFFFFu, v, 4);
                v += __shfl_xor_sync(0xFFFFFFFFu, v, 8);
                v += __shfl_xor_sync(0xFFFFFFFFu, v, 16);
                st[f][j] = v;
            }
        if (ln < 4) {
#pragma unroll
            for (int f = 0; f < 8; f++) {
                int c = cb + f * 8 + ln * 2;
                sstat[wid * 256 + c] = st[f][0];
                sstat[wid * 256 + c + 1] = st[f][1];
                sstat[wid * 256 + 128 + c] = st[f][2];
                sstat[wid * 256 + 128 + c + 1] = st[f][3];
            }
        }
        __syncthreads();
        if (tid < 256) {
            float tot = 0.f;
#pragma unroll
            for (int w8 = 0; w8 < 8; w8++) tot += sstat[w8 * 256 + tid];
            atomicAdd(&g_stats[tid], tot);
        }
    }
}

// ---------------- finalize + normalize ----------------
__global__ void finalize_kernel(const float* __restrict__ gamma,
                                const float* __restrict__ beta) {
    int c = threadIdx.x;
    float mean = g_stats[c] * (1.0f / NN);
    float var = g_stats[DD + c] * (1.0f / NN) - mean * mean;
    float sc = rsqrtf(var + BN_EPS) * gamma[c];
    g_scale[c] = sc;
    g_shift[c] = beta[c] - mean * sc;
}

__global__ void norm_kernel(float* __restrict__ out) {
    int i = blockIdx.x * blockDim.x + threadIdx.x;
    if (i >= NN * DD / 4) return;
    float4 v = ((const float4*)g_buf1)[i];
    float4 sc = ((const float4*)g_scale)[i & 31];
    float4 sh = ((const float4*)g_shift)[i & 31];
    v.x = v.x * sc.x + sh.x;
    v.y = v.y * sc.y + sh.y;
    v.z = v.z * sc.z + sh.z;
    v.w = v.w * sc.w + sh.w;
    ((float4*)out)[i] = v;
}

extern "C" void kernel_launch(void* const* d_in, const int* in_sizes, int n_in,
                              void* d_out, int out_size) {
    const float* x = (const float*)d_in[0];
    const void* ei = d_in[1];
    const float* ea = (const float*)d_in[2];
    const float* W1 = (const float*)d_in[3];
    const float* b1 = (const float*)d_in[4];
    const float* W2 = (const float*)d_in[5];
    const float* b2 = (const float*)d_in[6];
    const float* gamma = (const float*)d_in[7];
    const float* beta = (const float*)d_in[8];
    float* out = (float*)d_out;

    cudaFuncSetAttribute(mm_kernel<0>, cudaFuncAttributeMaxDynamicSharedMemorySize, MM_SMEM);
    cudaFuncSetAttribute(mm_kernel<1>, cudaFuncAttributeMaxDynamicSharedMemorySize, MM_SMEM);

    zero_kernel<<<(NN + 255) / 256, 256>>>((const int*)ei);
    prep_w<<<dim3(DD, 2), DD>>>(W1, W2);
    convert_kernel<<<(EE + 255) / 256, 256>>>(ei);
    scanA_kernel<<<SCAN_NB, SCAN_BLK>>>();
    scanB_kernel<<<1, 64>>>();
    scanC_kernel<<<SCAN_NB, SCAN_BLK>>>();
    scatter_kernel<<<(EE + 255) / 256, 256>>>();
    agg_kernel<<<(NN * 32 + 255) / 256, 256>>>(x, ea);
    mm_kernel<0><<<(NN + 63) / 64, 256, MM_SMEM>>>(b1, x);
    mm_kernel<1><<<(NN + 63) / 64, 256, MM_SMEM>>>(b2, x);
    finalize_kernel<<<1, DD>>>(gamma, beta);
    norm_kernel<<<(NN * DD / 4 + 255) / 256, 256>>>(out);
}

// round 16
// speedup vs baseline: 1.1397x; 1.0128x over previous
#include <cuda_runtime.h>
#include <cuda_bf16.h>
#include <cstdint>

#define NN 50000
#define DD 128
#define EE 800000
#define BN_EPS 1e-5f

// ---------------- scratch (no allocs allowed) ----------------
__device__ float g_buf1[NN * DD];          // agg -> h (pre-BN)
__device__ float g_buf2[NN * DD];          // t = relu(h@W1+b1)
__device__ float g_stats[2 * DD];
__device__ float g_scale[DD];
__device__ float g_shift[DD];
__device__ int g_is64;
__device__ __nv_bfloat16 g_w1hi[DD * DD];  // W^T hi/lo splits, [n][k] bf16
__device__ __nv_bfloat16 g_w1lo[DD * DD];
__device__ __nv_bfloat16 g_w2hi[DD * DD];
__device__ __nv_bfloat16 g_w2lo[DD * DD];
// CSR scratch
__device__ int g_src[EE];
__device__ int g_dst[EE];
__device__ int g_cnt[NN];
__device__ int g_off[NN];
__device__ int g_cursor[NN];
__device__ int2 g_pair[EE];                // {edge id, src} bucketed by dst
__device__ int g_bsum[64];                 // block sums for device-wide scan

#define SCAN_BLK 1024
#define SCAN_NB ((NN + SCAN_BLK - 1) / SCAN_BLK)   // 49

// ---------------- helpers ----------------
__device__ __forceinline__ uint32_t smem_u32(const void* p) {
    uint32_t a;
    asm("{ .reg .u64 t; cvta.to.shared.u64 t, %1; cvt.u32.u64 %0, t; }" : "=r"(a) : "l"(p));
    return a;
}
#define LDSM4(r, addr)                                                        \
    asm volatile("ldmatrix.sync.aligned.m8n8.x4.shared.b16 {%0,%1,%2,%3}, [%4];" \
                 : "=r"((r)[0]), "=r"((r)[1]), "=r"((r)[2]), "=r"((r)[3])     \
                 : "r"(addr))
#define MMA(ac, a, b0, b1)                                                    \
    asm volatile(                                                             \
        "mma.sync.aligned.m16n8k16.row.col.f32.bf16.bf16.f32 "                \
        "{%0,%1,%2,%3}, {%4,%5,%6,%7}, {%8,%9}, {%0,%1,%2,%3};"               \
        : "+f"((ac)[0]), "+f"((ac)[1]), "+f"((ac)[2]), "+f"((ac)[3])          \
        : "r"((a)[0]), "r"((a)[1]), "r"((a)[2]), "r"((a)[3]), "r"(b0), "r"(b1))

// ---------------- zero counters + stats + dtype probe ----------------
__global__ void zero_kernel(const int* __restrict__ ei32) {
    int i = blockIdx.x * blockDim.x + threadIdx.x;
    if (i < NN) g_cnt[i] = 0;
    if (i < 2 * DD) g_stats[i] = 0.f;
    if (blockIdx.x == 0 && threadIdx.x == 0) {
        int zeros = 0;
        for (int k = 1; k < 256; k += 2) zeros += (ei32[k] == 0);
        g_is64 = (zeros >= 96) ? 1 : 0;
    }
}

// ---------------- prep: W -> transposed bf16 hi/lo splits [n][k] ----------------
__global__ void prep_w(const float* __restrict__ W1, const float* __restrict__ W2) {
    const float* W = blockIdx.y ? W2 : W1;
    __nv_bfloat16* hi = blockIdx.y ? g_w2hi : g_w1hi;
    __nv_bfloat16* lo = blockIdx.y ? g_w2lo : g_w1lo;
    int k = blockIdx.x, n = threadIdx.x;
    float v = W[k * DD + n];
    __nv_bfloat16 h = __float2bfloat16(v);
    hi[n * DD + k] = h;
    lo[n * DD + k] = __float2bfloat16(v - __bfloat162float(h));
}

// ---------------- convert: edge_index -> int32 + dst histogram ----------------
__global__ void convert_kernel(const void* __restrict__ ei) {
    int e = blockIdx.x * blockDim.x + threadIdx.x;
    if (e >= EE) return;
    long long s, d;
    if (g_is64) {
        const long long* p = (const long long*)ei;
        s = p[e];
        d = p[EE + e];
    } else {
        const int* p = (const int*)ei;
        s = p[e];
        d = p[EE + e];
    }
    int si = (int)s, di = (int)d;
    if ((unsigned)si >= NN) si = 0;
    if ((unsigned)di >= NN) di = 0;
    g_src[e] = si;
    g_dst[e] = di;
    atomicAdd(&g_cnt[di], 1);
}

// ---------------- device-wide exclusive scan, 3 phases ----------------
__global__ void scanA_kernel() {
    __shared__ int warp_sums[32];
    int tid = threadIdx.x;
    int i = blockIdx.x * SCAN_BLK + tid;
    int v = (i < NN) ? g_cnt[i] : 0;
    int incl = v;
#pragma unroll
    for (int d = 1; d < 32; d <<= 1) {
        int t = __shfl_up_sync(0xFFFFFFFFu, incl, d);
        if ((tid & 31) >= d) incl += t;
    }
    if ((tid & 31) == 31) warp_sums[tid >> 5] = incl;
    __syncthreads();
    if (tid < 32) {
        int w = warp_sums[tid];
        int ws = w;
#pragma unroll
        for (int d = 1; d < 32; d <<= 1) {
            int t = __shfl_up_sync(0xFFFFFFFFu, ws, d);
            if (tid >= d) ws += t;
        }
        warp_sums[tid] = ws - w;  // exclusive warp offset
        if (tid == 31) g_bsum[blockIdx.x] = ws;  // block total
    }
    __syncthreads();
    int excl = incl - v + warp_sums[tid >> 5];
    if (i < NN) g_off[i] = excl;
}

__global__ void scanB_kernel() {
    __shared__ int w0tot;
    int tid = threadIdx.x;  // 64 threads
    int v = (tid < SCAN_NB) ? g_bsum[tid] : 0;
    int incl = v;
#pragma unroll
    for (int d = 1; d < 32; d <<= 1) {
        int t = __shfl_up_sync(0xFFFFFFFFu, incl, d);
        if ((tid & 31) >= d) incl += t;
    }
    if (tid == 31) w0tot = incl;
    __syncthreads();
    int excl = incl - v + ((tid >= 32) ? w0tot : 0);
    if (tid < SCAN_NB) g_bsum[tid] = excl;
}

__global__ void scanC_kernel() {
    int tid = threadIdx.x;
    int i = blockIdx.x * SCAN_BLK + tid;
    if (i >= NN) return;
    int o = g_off[i] + g_bsum[blockIdx.x];
    g_off[i] = o;
    g_cursor[i] = o;
}

// ---------------- scatter: bucket {edge, src} pairs by dst ----------------
__global__ void scatter_kernel() {
    int e = blockIdx.x * blockDim.x + threadIdx.x;
    if (e >= EE) return;
    int d = g_dst[e];
    int pos = atomicAdd(&g_cursor[d], 1);
    g_pair[pos] = make_int2(e, g_src[e]);
}

// ---------------- aggregate: warp/node, 4-pair prefetch, 2+2 consume ----------------
// (reduced live registers vs full unroll-4: 4 live float4s instead of 8 -> higher occupancy)
__global__ void agg_kernel(const float* __restrict__ x,
                           const float* __restrict__ ea) {
    int w = (blockIdx.x * blockDim.x + threadIdx.x) >> 5;
    int ln = threadIdx.x & 31;
    if (w >= NN) return;
    int beg = g_off[w];
    int cnt = g_cnt[w];
    int c = ln * 4;
    float4 acc = __ldg((const float4*)(x + (size_t)w * DD + c));  // h = x + agg
    const int2* pp = g_pair + beg;

    int i = 0;
    if (cnt >= 8) {
        int2 p0 = __ldg(pp + 0), p1 = __ldg(pp + 1);
        int2 p2 = __ldg(pp + 2), p3 = __ldg(pp + 3);
        for (; i + 7 < cnt; i += 4) {
            int2 n0 = __ldg(pp + i + 4), n1 = __ldg(pp + i + 5);
            int2 n2 = __ldg(pp + i + 6), n3 = __ldg(pp + i + 7);
            // batch 1: edges 0,1
            {
                float4 a0 = __ldcs((const float4*)(ea + (size_t)p0.x * DD + c));
                float4 b0 = __ldg((const float4*)(x + (size_t)p0.y * DD + c));
                float4 a1 = __ldcs((const float4*)(ea + (size_t)p1.x * DD + c));
                float4 b1 = __ldg((const float4*)(x + (size_t)p1.y * DD + c));
                acc.x += fmaxf(a0.x + b0.x, 0.f) + fmaxf(a1.x + b1.x, 0.f);
                acc.y += fmaxf(a0.y + b0.y, 0.f) + fmaxf(a1.y + b1.y, 0.f);
                acc.z += fmaxf(a0.z + b0.z, 0.f) + fmaxf(a1.z + b1.z, 0.f);
                acc.w += fmaxf(a0.w + b0.w, 0.f) + fmaxf(a1.w + b1.w, 0.f);
            }
            // batch 2: edges 2,3
            {
                float4 a2 = __ldcs((const float4*)(ea + (size_t)p2.x * DD + c));
                float4 b2 = __ldg((const float4*)(x + (size_t)p2.y * DD + c));
                float4 a3 = __ldcs((const float4*)(ea + (size_t)p3.x * DD + c));
                float4 b3 = __ldg((const float4*)(x + (size_t)p3.y * DD + c));
                acc.x += fmaxf(a2.x + b2.x, 0.f) + fmaxf(a3.x + b3.x, 0.f);
                acc.y += fmaxf(a2.y + b2.y, 0.f) + fmaxf(a3.y + b3.y, 0.f);
                acc.z += fmaxf(a2.z + b2.z, 0.f) + fmaxf(a3.z + b3.z, 0.f);
                acc.w += fmaxf(a2.w + b2.w, 0.f) + fmaxf(a3.w + b3.w, 0.f);
            }
            p0 = n0; p1 = n1; p2 = n2; p3 = n3;
        }
    }
    for (; i < cnt; i++) {
        int2 p = __ldg(pp + i);
        float4 a = __ldcs((const float4*)(ea + (size_t)p.x * DD + c));
        float4 b = __ldg((const float4*)(x + (size_t)p.y * DD + c));
        acc.x += fmaxf(a.x + b.x, 0.f);
        acc.y += fmaxf(a.y + b.y, 0.f);
        acc.z += fmaxf(a.z + b.z, 0.f);
        acc.w += fmaxf(a.w + b.w, 0.f);
    }
    *(float4*)(g_buf1 + (size_t)w * DD + c) = acc;
}

// ---------------- HMMA GEMM: 64x128 out tile per CTA, 2 CTAs/SM ----------------
// MODE 1 fuses BN column-stat accumulation (conflict-free: shfl butterfly +
// per-warp exclusive smem + one global atomic per thread).
#define AST 136
#define OF_AHI 1024u
#define OF_ALO (1024u + 17408u)
#define OF_BHI (1024u + 2u * 17408u)
#define OF_BLO (1024u + 2u * 17408u + 34816u)
#define MM_SMEM (1024 + 2 * 17408 + 2 * 34816)

template <int MODE>
__global__ void __launch_bounds__(256, 2) mm_kernel(const float* __restrict__ bias,
                                                    const float* __restrict__ resid) {
    extern __shared__ char smem[];
    const uint32_t sb = smem_u32(smem);
    float* sbias = (float*)smem;
    const int tid = threadIdx.x, wid = tid >> 5, ln = tid & 31;
    const int row0 = blockIdx.x * 64;

    const float* A = MODE ? g_buf2 : g_buf1;
    float* out = MODE ? g_buf1 : g_buf2;
    const __nv_bfloat16* Bhi = MODE ? g_w2hi : g_w1hi;
    const __nv_bfloat16* Blo = MODE ? g_w2lo : g_w1lo;

    if (tid < 128) sbias[tid] = bias[tid];

    {
        __nv_bfloat16* sAh = (__nv_bfloat16*)(smem + OF_AHI);
        __nv_bfloat16* sAl = (__nv_bfloat16*)(smem + OF_ALO);
#pragma unroll
        for (int rr = 0; rr < 8; rr++) {
            int r = wid * 8 + rr;
            int gr = row0 + r;
            float4 v = make_float4(0.f, 0.f, 0.f, 0.f);
            if (gr < NN) v = *(const float4*)(A + (size_t)gr * DD + ln * 4);
            __nv_bfloat16 hx = __float2bfloat16(v.x), hy = __float2bfloat16(v.y);
            __nv_bfloat16 hz = __float2bfloat16(v.z), hw = __float2bfloat16(v.w);
            __nv_bfloat162 hi0 = __halves2bfloat162(hx, hy);
            __nv_bfloat162 hi1 = __halves2bfloat162(hz, hw);
            __nv_bfloat162 lo0 = __halves2bfloat162(
                __float2bfloat16(v.x - __bfloat162float(hx)),
                __float2bfloat16(v.y - __bfloat162float(hy)));
            __nv_bfloat162 lo1 = __halves2bfloat162(
                __float2bfloat16(v.z - __bfloat162float(hz)),
                __float2bfloat16(v.w - __bfloat162float(hw)));
            int o = r * AST + ln * 4;
            *(__nv_bfloat162*)(sAh + o) = hi0;
            *(__nv_bfloat162*)(sAh + o + 2) = hi1;
            *(__nv_bfloat162*)(sAl + o) = lo0;
            *(__nv_bfloat162*)(sAl + o + 2) = lo1;
        }
    }
    {
        __nv_bfloat16* sBh = (__nv_bfloat16*)(smem + OF_BHI);
        __nv_bfloat16* sBl = (__nv_bfloat16*)(smem + OF_BLO);
#pragma unroll
        for (int rr = 0; rr < 16; rr++) {
            int n = wid * 16 + rr;
            uint2 vh = *(const uint2*)(Bhi + (size_t)n * DD + ln * 4);
            uint2 vl = *(const uint2*)(Blo + (size_t)n * DD + ln * 4);
            int o = n * AST + ln * 4;
            *(uint32_t*)((char*)sBh + (size_t)o * 2) = vh.x;
            *(uint32_t*)((char*)sBh + (size_t)o * 2 + 4) = vh.y;
            *(uint32_t*)((char*)sBl + (size_t)o * 2) = vl.x;
            *(uint32_t*)((char*)sBl + (size_t)o * 2 + 4) = vl.y;
        }
    }
    __syncthreads();

    const int m0 = (wid & 3) * 16;
    const int cb = (wid >> 2) * 64;
    const uint32_t a_off =
        (uint32_t)((m0 + ((ln >> 3) & 1) * 8 + (ln & 7)) * AST + ((ln >> 4) & 1) * 8) * 2u;
    const uint32_t b_off =
        (uint32_t)((cb + ((ln >> 4) & 1) * 8 + (ln & 7)) * AST + ((ln >> 3) & 1) * 8) * 2u;
    const uint32_t aAh = sb + OF_AHI + a_off, aAl = sb + OF_ALO + a_off;
    const uint32_t aBh = sb + OF_BHI + b_off, aBl = sb + OF_BLO + b_off;

    float acc[8][4];
#pragma unroll
    for (int f = 0; f < 8; f++)
#pragma unroll
        for (int j = 0; j < 4; j++) acc[f][j] = 0.f;

#pragma unroll
    for (int ks = 0; ks < 8; ks++) {
        const uint32_t kb = ks * 32u;
        uint32_t ah[4], al[4];
        LDSM4(ah, aAh + kb);
        LDSM4(al, aAl + kb);
#pragma unroll
        for (int nb = 0; nb < 4; nb++) {
            uint32_t bh[4], bl[4];
            const uint32_t bo = (uint32_t)(nb * 16 * AST) * 2u + kb;
            LDSM4(bh, aBh + bo);
            LDSM4(bl, aBl + bo);
            MMA(acc[2 * nb], ah, bh[0], bh[1]);
            MMA(acc[2 * nb + 1], ah, bh[2], bh[3]);
            MMA(acc[2 * nb], ah, bl[0], bl[1]);
            MMA(acc[2 * nb + 1], ah, bl[2], bl[3]);
            MMA(acc[2 * nb], al, bh[0], bh[1]);
            MMA(acc[2 * nb + 1], al, bh[2], bh[3]);
        }
    }

    // MODE 1: reuse A-tile smem for per-warp stats partials [8][256]
    float* sstat = (float*)(smem + OF_AHI);
    if (MODE == 1) {
        __syncthreads();  // all warps done reading tile smem
#pragma unroll
        for (int z = tid; z < 2048; z += 256) sstat[z] = 0.f;
        __syncthreads();
    }

    float st[8][4];  // per f: {sum.x, sum.y, sq.x, sq.y} (MODE 1 only)
    const int gr0 = row0 + m0 + (ln >> 2);
    const int gr1 = gr0 + 8;
#pragma unroll
    for (int f = 0; f < 8; f++) {
        const int c = cb + f * 8 + (ln & 3) * 2;
        float2 v0 = make_float2(acc[f][0] + sbias[c], acc[f][1] + sbias[c + 1]);
        float2 v1 = make_float2(acc[f][2] + sbias[c], acc[f][3] + sbias[c + 1]);
        if (MODE == 0) {
            v0.x = fmaxf(v0.x, 0.f); v0.y = fmaxf(v0.y, 0.f);
            v1.x = fmaxf(v1.x, 0.f); v1.y = fmaxf(v1.y, 0.f);
            if (gr0 < NN) *(float2*)(out + (size_t)gr0 * DD + c) = v0;
            if (gr1 < NN) *(float2*)(out + (size_t)gr1 * DD + c) = v1;
        } else {
            bool ok0 = gr0 < NN, ok1 = gr1 < NN;
            if (ok0) {
                float2 r = *(const float2*)(resid + (size_t)gr0 * DD + c);
                v0.x += r.x; v0.y += r.y;
                *(float2*)(out + (size_t)gr0 * DD + c) = v0;
            }
            if (ok1) {
                float2 r = *(const float2*)(resid + (size_t)gr1 * DD + c);
                v1.x += r.x; v1.y += r.y;
                *(float2*)(out + (size_t)gr1 * DD + c) = v1;
            }
            float x0 = ok0 ? v0.x : 0.f, y0 = ok0 ? v0.y : 0.f;
            float x1 = ok1 ? v1.x : 0.f, y1 = ok1 ? v1.y : 0.f;
            st[f][0] = x0 + x1;
            st[f][1] = y0 + y1;
            st[f][2] = x0 * x0 + x1 * x1;
            st[f][3] = y0 * y0 + y1 * y1;
        }
    }

    if (MODE == 1) {
        // butterfly-reduce over the 8 lanes sharing each column (ln^4, ln^8, ln^16)
#pragma unroll
        for (int f = 0; f < 8; f++)
#pragma unroll
            for (int j = 0; j < 4; j++) {
                float v = st[f][j];
                v += __shfl_xor_sync(0xFFFFFFFFu, v, 4);
                v += __shfl_xor_sync(0xFFFFFFFFu, v, 8);
                v += __shfl_xor_sync(0xFFFFFFFFu, v, 16);
                st[f][j] = v;
            }
        if (ln < 4) {
#pragma unroll
            for (int f = 0; f < 8; f++) {
                int c = cb + f * 8 + ln * 2;
                sstat[wid * 256 + c] = st[f][0];
                sstat[wid * 256 + c + 1] = st[f][1];
                sstat[wid * 256 + 128 + c] = st[f][2];
                sstat[wid * 256 + 128 + c + 1] = st[f][3];
            }
        }
        __syncthreads();
        if (tid < 256) {
            float tot = 0.f;
#pragma unroll
            for (int w8 = 0; w8 < 8; w8++) tot += sstat[w8 * 256 + tid];
            atomicAdd(&g_stats[tid], tot);
        }
    }
}

// ---------------- finalize + normalize ----------------
__global__ void finalize_kernel(const float* __restrict__ gamma,
                                const float* __restrict__ beta) {
    int c = threadIdx.x;
    float mean = g_stats[c] * (1.0f / NN);
    float var = g_stats[DD + c] * (1.0f / NN) - mean * mean;
    float sc = rsqrtf(var + BN_EPS) * gamma[c];
    g_scale[c] = sc;
    g_shift[c] = beta[c] - mean * sc;
}

__global__ void norm_kernel(float* __restrict__ out) {
    int i = blockIdx.x * blockDim.x + threadIdx.x;
    if (i >= NN * DD / 4) return;
    float4 v = ((const float4*)g_buf1)[i];
    float4 sc = ((const float4*)g_scale)[i & 31];
    float4 sh = ((const float4*)g_shift)[i & 31];
    v.x = v.x * sc.x + sh.x;
    v.y = v.y * sc.y + sh.y;
    v.z = v.z * sc.z + sh.z;
    v.w = v.w * sc.w + sh.w;
    ((float4*)out)[i] = v;
}

extern "C" void kernel_launch(void* const* d_in, const int* in_sizes, int n_in,
                              void* d_out, int out_size) {
    const float* x = (const float*)d_in[0];
    const void* ei = d_in[1];
    const float* ea = (const float*)d_in[2];
    const float* W1 = (const float*)d_in[3];
    const float* b1 = (const float*)d_in[4];
    const float* W2 = (const float*)d_in[5];
    const float* b2 = (const float*)d_in[6];
    const float* gamma = (const float*)d_in[7];
    const float* beta = (const float*)d_in[8];
    float* out = (float*)d_out;

    cudaFuncSetAttribute(mm_kernel<0>, cudaFuncAttributeMaxDynamicSharedMemorySize, MM_SMEM);
    cudaFuncSetAttribute(mm_kernel<1>, cudaFuncAttributeMaxDynamicSharedMemorySize, MM_SMEM);

    zero_kernel<<<(NN + 255) / 256, 256>>>((const int*)ei);
    prep_w<<<dim3(DD, 2), DD>>>(W1, W2);
    convert_kernel<<<(EE + 255) / 256, 256>>>(ei);
    scanA_kernel<<<SCAN_NB, SCAN_BLK>>>();
    scanB_kernel<<<1, 64>>>();
    scanC_kernel<<<SCAN_NB, SCAN_BLK>>>();
    scatter_kernel<<<(EE + 255) / 256, 256>>>();
    agg_kernel<<<(NN * 32 + 255) / 256, 256>>>(x, ea);
    mm_kernel<0><<<(NN + 63) / 64, 256, MM_SMEM>>>(b1, x);
    mm_kernel<1><<<(NN + 63) / 64, 256, MM_SMEM>>>(b2, x);
    finalize_kernel<<<1, DD>>>(gamma, beta);
    norm_kernel<<<(NN * DD / 4 + 255) / 256, 256>>>(out);
}

// round 17
// speedup vs baseline: 1.1526x; 1.0113x over previous
#include <cuda_runtime.h>
#include <cuda_bf16.h>
#include <cstdint>

#define NN 50000
#define DD 128
#define EE 800000
#define BN_EPS 1e-5f

// ---------------- scratch (no allocs allowed) ----------------
__device__ float g_buf1[NN * DD];          // agg -> h (pre-BN)
__device__ float g_stats[2 * DD];
__device__ float g_scale[DD];
__device__ float g_shift[DD];
__device__ int g_is64;
__device__ __nv_bfloat16 g_w1hi[DD * DD];  // W^T hi/lo splits, [n][k] bf16
__device__ __nv_bfloat16 g_w1lo[DD * DD];
__device__ __nv_bfloat16 g_w2hi[DD * DD];
__device__ __nv_bfloat16 g_w2lo[DD * DD];
// CSR scratch
__device__ int g_src[EE];
__device__ int g_dst[EE];
__device__ int g_cnt[NN];
__device__ int g_off[NN];
__device__ int g_cursor[NN];
__device__ int2 g_pair[EE];                // {edge id, src} bucketed by dst
__device__ int g_bsum[64];                 // block sums for device-wide scan

#define SCAN_BLK 1024
#define SCAN_NB ((NN + SCAN_BLK - 1) / SCAN_BLK)   // 49

// ---------------- helpers ----------------
__device__ __forceinline__ uint32_t smem_u32(const void* p) {
    uint32_t a;
    asm("{ .reg .u64 t; cvta.to.shared.u64 t, %1; cvt.u32.u64 %0, t; }" : "=r"(a) : "l"(p));
    return a;
}
#define LDSM4(r, addr)                                                        \
    asm volatile("ldmatrix.sync.aligned.m8n8.x4.shared.b16 {%0,%1,%2,%3}, [%4];" \
                 : "=r"((r)[0]), "=r"((r)[1]), "=r"((r)[2]), "=r"((r)[3])     \
                 : "r"(addr))
#define MMA(ac, a, b0, b1)                                                    \
    asm volatile(                                                             \
        "mma.sync.aligned.m16n8k16.row.col.f32.bf16.bf16.f32 "                \
        "{%0,%1,%2,%3}, {%4,%5,%6,%7}, {%8,%9}, {%0,%1,%2,%3};"               \
        : "+f"((ac)[0]), "+f"((ac)[1]), "+f"((ac)[2]), "+f"((ac)[3])          \
        : "r"((a)[0]), "r"((a)[1]), "r"((a)[2]), "r"((a)[3]), "r"(b0), "r"(b1))

// ---------------- zero counters + stats + dtype probe ----------------
__global__ void zero_kernel(const int* __restrict__ ei32) {
    int i = blockIdx.x * blockDim.x + threadIdx.x;
    if (i < NN) g_cnt[i] = 0;
    if (i < 2 * DD) g_stats[i] = 0.f;
    if (blockIdx.x == 0 && threadIdx.x == 0) {
        int zeros = 0;
        for (int k = 1; k < 256; k += 2) zeros += (ei32[k] == 0);
        g_is64 = (zeros >= 96) ? 1 : 0;
    }
}

// ---------------- prep: W -> transposed bf16 hi/lo splits [n][k] ----------------
__global__ void prep_w(const float* __restrict__ W1, const float* __restrict__ W2) {
    const float* W = blockIdx.y ? W2 : W1;
    __nv_bfloat16* hi = blockIdx.y ? g_w2hi : g_w1hi;
    __nv_bfloat16* lo = blockIdx.y ? g_w2lo : g_w1lo;
    int k = blockIdx.x, n = threadIdx.x;
    float v = W[k * DD + n];
    __nv_bfloat16 h = __float2bfloat16(v);
    hi[n * DD + k] = h;
    lo[n * DD + k] = __float2bfloat16(v - __bfloat162float(h));
}

// ---------------- convert: edge_index -> int32 + dst histogram ----------------
__global__ void convert_kernel(const void* __restrict__ ei) {
    int e = blockIdx.x * blockDim.x + threadIdx.x;
    if (e >= EE) return;
    long long s, d;
    if (g_is64) {
        const long long* p = (const long long*)ei;
        s = p[e];
        d = p[EE + e];
    } else {
        const int* p = (const int*)ei;
        s = p[e];
        d = p[EE + e];
    }
    int si = (int)s, di = (int)d;
    if ((unsigned)si >= NN) si = 0;
    if ((unsigned)di >= NN) di = 0;
    g_src[e] = si;
    g_dst[e] = di;
    atomicAdd(&g_cnt[di], 1);
}

// ---------------- device-wide exclusive scan, 3 phases ----------------
__global__ void scanA_kernel() {
    __shared__ int warp_sums[32];
    int tid = threadIdx.x;
    int i = blockIdx.x * SCAN_BLK + tid;
    int v = (i < NN) ? g_cnt[i] : 0;
    int incl = v;
#pragma unroll
    for (int d = 1; d < 32; d <<= 1) {
        int t = __shfl_up_sync(0xFFFFFFFFu, incl, d);
        if ((tid & 31) >= d) incl += t;
    }
    if ((tid & 31) == 31) warp_sums[tid >> 5] = incl;
    __syncthreads();
    if (tid < 32) {
        int w = warp_sums[tid];
        int ws = w;
#pragma unroll
        for (int d = 1; d < 32; d <<= 1) {
            int t = __shfl_up_sync(0xFFFFFFFFu, ws, d);
            if (tid >= d) ws += t;
        }
        warp_sums[tid] = ws - w;  // exclusive warp offset
        if (tid == 31) g_bsum[blockIdx.x] = ws;  // block total
    }
    __syncthreads();
    int excl = incl - v + warp_sums[tid >> 5];
    if (i < NN) g_off[i] = excl;
}

__global__ void scanB_kernel() {
    __shared__ int w0tot;
    int tid = threadIdx.x;  // 64 threads
    int v = (tid < SCAN_NB) ? g_bsum[tid] : 0;
    int incl = v;
#pragma unroll
    for (int d = 1; d < 32; d <<= 1) {
        int t = __shfl_up_sync(0xFFFFFFFFu, incl, d);
        if ((tid & 31) >= d) incl += t;
    }
    if (tid == 31) w0tot = incl;
    __syncthreads();
    int excl = incl - v + ((tid >= 32) ? w0tot : 0);
    if (tid < SCAN_NB) g_bsum[tid] = excl;
}

__global__ void scanC_kernel() {
    int tid = threadIdx.x;
    int i = blockIdx.x * SCAN_BLK + tid;
    if (i >= NN) return;
    int o = g_off[i] + g_bsum[blockIdx.x];
    g_off[i] = o;
    g_cursor[i] = o;
}

// ---------------- scatter: bucket {edge, src} pairs by dst ----------------
__global__ void scatter_kernel() {
    int e = blockIdx.x * blockDim.x + threadIdx.x;
    if (e >= EE) return;
    int d = g_dst[e];
    int pos = atomicAdd(&g_cursor[d], 1);
    g_pair[pos] = make_int2(e, g_src[e]);
}

// ---------------- aggregate: warp/node, 4-pair prefetch, 2+2 consume ----------------
__global__ void agg_kernel(const float* __restrict__ x,
                           const float* __restrict__ ea) {
    int w = (blockIdx.x * blockDim.x + threadIdx.x) >> 5;
    int ln = threadIdx.x & 31;
    if (w >= NN) return;
    int beg = g_off[w];
    int cnt = g_cnt[w];
    int c = ln * 4;
    float4 acc = __ldg((const float4*)(x + (size_t)w * DD + c));  // h = x + agg
    const int2* pp = g_pair + beg;

    int i = 0;
    if (cnt >= 8) {
        int2 p0 = __ldg(pp + 0), p1 = __ldg(pp + 1);
        int2 p2 = __ldg(pp + 2), p3 = __ldg(pp + 3);
        for (; i + 7 < cnt; i += 4) {
            int2 n0 = __ldg(pp + i + 4), n1 = __ldg(pp + i + 5);
            int2 n2 = __ldg(pp + i + 6), n3 = __ldg(pp + i + 7);
            {
                float4 a0 = __ldcs((const float4*)(ea + (size_t)p0.x * DD + c));
                float4 b0 = __ldg((const float4*)(x + (size_t)p0.y * DD + c));
                float4 a1 = __ldcs((const float4*)(ea + (size_t)p1.x * DD + c));
                float4 b1 = __ldg((const float4*)(x + (size_t)p1.y * DD + c));
                acc.x += fmaxf(a0.x + b0.x, 0.f) + fmaxf(a1.x + b1.x, 0.f);
                acc.y += fmaxf(a0.y + b0.y, 0.f) + fmaxf(a1.y + b1.y, 0.f);
                acc.z += fmaxf(a0.z + b0.z, 0.f) + fmaxf(a1.z + b1.z, 0.f);
                acc.w += fmaxf(a0.w + b0.w, 0.f) + fmaxf(a1.w + b1.w, 0.f);
            }
            {
                float4 a2 = __ldcs((const float4*)(ea + (size_t)p2.x * DD + c));
                float4 b2 = __ldg((const float4*)(x + (size_t)p2.y * DD + c));
                float4 a3 = __ldcs((const float4*)(ea + (size_t)p3.x * DD + c));
                float4 b3 = __ldg((const float4*)(x + (size_t)p3.y * DD + c));
                acc.x += fmaxf(a2.x + b2.x, 0.f) + fmaxf(a3.x + b3.x, 0.f);
                acc.y += fmaxf(a2.y + b2.y, 0.f) + fmaxf(a3.y + b3.y, 0.f);
                acc.z += fmaxf(a2.z + b2.z, 0.f) + fmaxf(a3.z + b3.z, 0.f);
                acc.w += fmaxf(a2.w + b2.w, 0.f) + fmaxf(a3.w + b3.w, 0.f);
            }
            p0 = n0; p1 = n1; p2 = n2; p3 = n3;
        }
    }
    for (; i < cnt; i++) {
        int2 p = __ldg(pp + i);
        float4 a = __ldcs((const float4*)(ea + (size_t)p.x * DD + c));
        float4 b = __ldg((const float4*)(x + (size_t)p.y * DD + c));
        acc.x += fmaxf(a.x + b.x, 0.f);
        acc.y += fmaxf(a.y + b.y, 0.f);
        acc.z += fmaxf(a.z + b.z, 0.f);
        acc.w += fmaxf(a.w + b.w, 0.f);
    }
    *(float4*)(g_buf1 + (size_t)w * DD + c) = acc;
}

// ---------------- fused MLP: both GEMMs in one kernel, t stays on-chip ----------
// Stage 1: t = relu(h@W1 + b1)   (h = g_buf1 tile, t -> smem as bf16 hi/lo)
// Stage 2: g_buf1 = x + t@W2 + b2, fused BN stats.
// smem: bias (b1,b2) | A hi/lo (reused for t) | B1 hi/lo | B2 hi/lo = 171 KB, 1 CTA/SM
#define AST 136
#define OF_AHI 1024u
#define OF_ALO (1024u + 17408u)
#define OF_B1H (1024u + 2u * 17408u)
#define OF_B1L (OF_B1H + 34816u)
#define OF_B2H (OF_B1L + 34816u)
#define OF_B2L (OF_B2H + 34816u)
#define MM_SMEM (1024 + 2 * 17408 + 4 * 34816)

__global__ void __launch_bounds__(256, 1) mlp_kernel(const float* __restrict__ b1,
                                                     const float* __restrict__ b2,
                                                     const float* __restrict__ resid) {
    extern __shared__ char smem[];
    const uint32_t sb = smem_u32(smem);
    float* sb1 = (float*)smem;        // [128]
    float* sb2 = sb1 + 128;           // [128]
    const int tid = threadIdx.x, wid = tid >> 5, ln = tid & 31;
    const int row0 = blockIdx.x * 64;

    if (tid < 128) sb1[tid] = b1[tid];
    else sb2[tid - 128] = b2[tid - 128];

    // A: 64 rows of g_buf1, fp32 -> bf16 hi/lo, padded [m][AST]
    {
        __nv_bfloat16* sAh = (__nv_bfloat16*)(smem + OF_AHI);
        __nv_bfloat16* sAl = (__nv_bfloat16*)(smem + OF_ALO);
#pragma unroll
        for (int rr = 0; rr < 8; rr++) {
            int r = wid * 8 + rr;
            int gr = row0 + r;
            float4 v = make_float4(0.f, 0.f, 0.f, 0.f);
            if (gr < NN) v = *(const float4*)(g_buf1 + (size_t)gr * DD + ln * 4);
            __nv_bfloat16 hx = __float2bfloat16(v.x), hy = __float2bfloat16(v.y);
            __nv_bfloat16 hz = __float2bfloat16(v.z), hw = __float2bfloat16(v.w);
            __nv_bfloat162 hi0 = __halves2bfloat162(hx, hy);
            __nv_bfloat162 hi1 = __halves2bfloat162(hz, hw);
            __nv_bfloat162 lo0 = __halves2bfloat162(
                __float2bfloat16(v.x - __bfloat162float(hx)),
                __float2bfloat16(v.y - __bfloat162float(hy)));
            __nv_bfloat162 lo1 = __halves2bfloat162(
                __float2bfloat16(v.z - __bfloat162float(hz)),
                __float2bfloat16(v.w - __bfloat162float(hw)));
            int o = r * AST + ln * 4;
            *(__nv_bfloat162*)(sAh + o) = hi0;
            *(__nv_bfloat162*)(sAh + o + 2) = hi1;
            *(__nv_bfloat162*)(sAl + o) = lo0;
            *(__nv_bfloat162*)(sAl + o + 2) = lo1;
        }
    }
    // B1 and B2 tiles (pre-split bf16 [n][k] -> padded [n][AST])
    {
#pragma unroll
        for (int rr = 0; rr < 16; rr++) {
            int n = wid * 16 + rr;
            size_t go = (size_t)n * DD + ln * 4;
            size_t so = ((size_t)(n * AST + ln * 4)) * 2;
            uint2 v;
            v = *(const uint2*)(g_w1hi + go);
            *(uint32_t*)(smem + OF_B1H + so) = v.x;
            *(uint32_t*)(smem + OF_B1H + so + 4) = v.y;
            v = *(const uint2*)(g_w1lo + go);
            *(uint32_t*)(smem + OF_B1L + so) = v.x;
            *(uint32_t*)(smem + OF_B1L + so + 4) = v.y;
            v = *(const uint2*)(g_w2hi + go);
            *(uint32_t*)(smem + OF_B2H + so) = v.x;
            *(uint32_t*)(smem + OF_B2H + so + 4) = v.y;
            v = *(const uint2*)(g_w2lo + go);
            *(uint32_t*)(smem + OF_B2L + so) = v.x;
            *(uint32_t*)(smem + OF_B2L + so + 4) = v.y;
        }
    }
    __syncthreads();

    const int m0 = (wid & 3) * 16;
    const int cb = (wid >> 2) * 64;
    const uint32_t a_off =
        (uint32_t)((m0 + ((ln >> 3) & 1) * 8 + (ln & 7)) * AST + ((ln >> 4) & 1) * 8) * 2u;
    const uint32_t b_off =
        (uint32_t)((cb + ((ln >> 4) & 1) * 8 + (ln & 7)) * AST + ((ln >> 3) & 1) * 8) * 2u;
    const uint32_t aAh = sb + OF_AHI + a_off, aAl = sb + OF_ALO + a_off;

    float acc[8][4];

    // ---------------- stage 1: h @ W1 ----------------
#pragma unroll
    for (int f = 0; f < 8; f++)
#pragma unroll
        for (int j = 0; j < 4; j++) acc[f][j] = 0.f;
    {
        const uint32_t aBh = sb + OF_B1H + b_off, aBl = sb + OF_B1L + b_off;
#pragma unroll
        for (int ks = 0; ks < 8; ks++) {
            const uint32_t kb = ks * 32u;
            uint32_t ah[4], al[4];
            LDSM4(ah, aAh + kb);
            LDSM4(al, aAl + kb);
#pragma unroll
            for (int nb = 0; nb < 4; nb++) {
                uint32_t bh[4], bl[4];
                const uint32_t bo = (uint32_t)(nb * 16 * AST) * 2u + kb;
                LDSM4(bh, aBh + bo);
                LDSM4(bl, aBl + bo);
                MMA(acc[2 * nb], ah, bh[0], bh[1]);
                MMA(acc[2 * nb + 1], ah, bh[2], bh[3]);
                MMA(acc[2 * nb], ah, bl[0], bl[1]);
                MMA(acc[2 * nb + 1], ah, bl[2], bl[3]);
                MMA(acc[2 * nb], al, bh[0], bh[1]);
                MMA(acc[2 * nb + 1], al, bh[2], bh[3]);
            }
        }
    }

    // t = relu(acc + b1) -> overwrite A smem as bf16 hi/lo (same split as before)
    __syncthreads();  // all warps done reading sA for stage 1
    {
        __nv_bfloat16* sAh = (__nv_bfloat16*)(smem + OF_AHI);
        __nv_bfloat16* sAl = (__nv_bfloat16*)(smem + OF_ALO);
        const int r0l = m0 + (ln >> 2);
        const int r1l = r0l + 8;
#pragma unroll
        for (int f = 0; f < 8; f++) {
            const int c = cb + f * 8 + (ln & 3) * 2;
            float t00 = fmaxf(acc[f][0] + sb1[c], 0.f);
            float t01 = fmaxf(acc[f][1] + sb1[c + 1], 0.f);
            float t10 = fmaxf(acc[f][2] + sb1[c], 0.f);
            float t11 = fmaxf(acc[f][3] + sb1[c + 1], 0.f);
            __nv_bfloat16 h00 = __float2bfloat16(t00), h01 = __float2bfloat16(t01);
            __nv_bfloat16 h10 = __float2bfloat16(t10), h11 = __float2bfloat16(t11);
            *(__nv_bfloat162*)(sAh + r0l * AST + c) = __halves2bfloat162(h00, h01);
            *(__nv_bfloat162*)(sAh + r1l * AST + c) = __halves2bfloat162(h10, h11);
            *(__nv_bfloat162*)(sAl + r0l * AST + c) = __halves2bfloat162(
                __float2bfloat16(t00 - __bfloat162float(h00)),
                __float2bfloat16(t01 - __bfloat162float(h01)));
            *(__nv_bfloat162*)(sAl + r1l * AST + c) = __halves2bfloat162(
                __float2bfloat16(t10 - __bfloat162float(h10)),
                __float2bfloat16(t11 - __bfloat162float(h11)));
        }
    }
    __syncthreads();  // t fully written before stage-2 ldmatrix

    // ---------------- stage 2: t @ W2 ----------------
#pragma unroll
    for (int f = 0; f < 8; f++)
#pragma unroll
        for (int j = 0; j < 4; j++) acc[f][j] = 0.f;
    {
        const uint32_t aBh = sb + OF_B2H + b_off, aBl = sb + OF_B2L + b_off;
#pragma unroll
        for (int ks = 0; ks < 8; ks++) {
            const uint32_t kb = ks * 32u;
            uint32_t ah[4], al[4];
            LDSM4(ah, aAh + kb);
            LDSM4(al, aAl + kb);
#pragma unroll
            for (int nb = 0; nb < 4; nb++) {
                uint32_t bh[4], bl[4];
                const uint32_t bo = (uint32_t)(nb * 16 * AST) * 2u + kb;
                LDSM4(bh, aBh + bo);
                LDSM4(bl, aBl + bo);
                MMA(acc[2 * nb], ah, bh[0], bh[1]);
                MMA(acc[2 * nb + 1], ah, bh[2], bh[3]);
                MMA(acc[2 * nb], ah, bl[0], bl[1]);
                MMA(acc[2 * nb + 1], ah, bl[2], bl[3]);
                MMA(acc[2 * nb], al, bh[0], bh[1]);
                MMA(acc[2 * nb + 1], al, bh[2], bh[3]);
            }
        }
    }

    // epilogue: out = resid + acc + b2, fused conflict-free BN stats
    float* sstat = (float*)(smem + OF_AHI);  // reuse A region after stage 2
    __syncthreads();
#pragma unroll
    for (int z = tid; z < 2048; z += 256) sstat[z] = 0.f;
    __syncthreads();

    float st[8][4];
    const int gr0 = row0 + m0 + (ln >> 2);
    const int gr1 = gr0 + 8;
#pragma unroll
    for (int f = 0; f < 8; f++) {
        const int c = cb + f * 8 + (ln & 3) * 2;
        float2 v0 = make_float2(acc[f][0] + sb2[c], acc[f][1] + sb2[c + 1]);
        float2 v1 = make_float2(acc[f][2] + sb2[c], acc[f][3] + sb2[c + 1]);
        bool ok0 = gr0 < NN, ok1 = gr1 < NN;
        if (ok0) {
            float2 r = *(const float2*)(resid + (size_t)gr0 * DD + c);
            v0.x += r.x; v0.y += r.y;
            *(float2*)(g_buf1 + (size_t)gr0 * DD + c) = v0;
        }
        if (ok1) {
            float2 r = *(const float2*)(resid + (size_t)gr1 * DD + c);
            v1.x += r.x; v1.y += r.y;
            *(float2*)(g_buf1 + (size_t)gr1 * DD + c) = v1;
        }
        float x0 = ok0 ? v0.x : 0.f, y0 = ok0 ? v0.y : 0.f;
        float x1 = ok1 ? v1.x : 0.f, y1 = ok1 ? v1.y : 0.f;
        st[f][0] = x0 + x1;
        st[f][1] = y0 + y1;
        st[f][2] = x0 * x0 + x1 * x1;
        st[f][3] = y0 * y0 + y1 * y1;
    }

#pragma unroll
    for (int f = 0; f < 8; f++)
#pragma unroll
        for (int j = 0; j < 4; j++) {
            float v = st[f][j];
            v += __shfl_xor_sync(0xFFFFFFFFu, v, 4);
            v += __shfl_xor_sync(0xFFFFFFFFu, v, 8);
            v += __shfl_xor_sync(0xFFFFFFFFu, v, 16);
            st[f][j] = v;
        }
    if (ln < 4) {
#pragma unroll
        for (int f = 0; f < 8; f++) {
            int c = cb + f * 8 + ln * 2;
            sstat[wid * 256 + c] = st[f][0];
            sstat[wid * 256 + c + 1] = st[f][1];
            sstat[wid * 256 + 128 + c] = st[f][2];
            sstat[wid * 256 + 128 + c + 1] = st[f][3];
        }
    }
    __syncthreads();
    if (tid < 256) {
        float tot = 0.f;
#pragma unroll
        for (int w8 = 0; w8 < 8; w8++) tot += sstat[w8 * 256 + tid];
        atomicAdd(&g_stats[tid], tot);
    }
}

// ---------------- finalize + normalize ----------------
__global__ void finalize_kernel(const float* __restrict__ gamma,
                                const float* __restrict__ beta) {
    int c = threadIdx.x;
    float mean = g_stats[c] * (1.0f / NN);
    float var = g_stats[DD + c] * (1.0f / NN) - mean * mean;
    float sc = rsqrtf(var + BN_EPS) * gamma[c];
    g_scale[c] = sc;
    g_shift[c] = beta[c] - mean * sc;
}

__global__ void norm_kernel(float* __restrict__ out) {
    int i = blockIdx.x * blockDim.x + threadIdx.x;
    if (i >= NN * DD / 4) return;
    float4 v = ((const float4*)g_buf1)[i];
    float4 sc = ((const float4*)g_scale)[i & 31];
    float4 sh = ((const float4*)g_shift)[i & 31];
    v.x = v.x * sc.x + sh.x;
    v.y = v.y * sc.y + sh.y;
    v.z = v.z * sc.z + sh.z;
    v.w = v.w * sc.w + sh.w;
    ((float4*)out)[i] = v;
}

extern "C" void kernel_launch(void* const* d_in, const int* in_sizes, int n_in,
                              void* d_out, int out_size) {
    const float* x = (const float*)d_in[0];
    const void* ei = d_in[1];
    const float* ea = (const float*)d_in[2];
    const float* W1 = (const float*)d_in[3];
    const float* b1 = (const float*)d_in[4];
    const float* W2 = (const float*)d_in[5];
    const float* b2 = (const float*)d_in[6];
    const float* gamma = (const float*)d_in[7];
    const float* beta = (const float*)d_in[8];
    float* out = (float*)d_out;

    cudaFuncSetAttribute(mlp_kernel, cudaFuncAttributeMaxDynamicSharedMemorySize, MM_SMEM);

    zero_kernel<<<(NN + 255) / 256, 256>>>((const int*)ei);
    prep_w<<<dim3(DD, 2), DD>>>(W1, W2);
    convert_kernel<<<(EE + 255) / 256, 256>>>(ei);
    scanA_kernel<<<SCAN_NB, SCAN_BLK>>>();
    scanB_kernel<<<1, 64>>>();
    scanC_kernel<<<SCAN_NB, SCAN_BLK>>>();
    scatter_kernel<<<(EE + 255) / 256, 256>>>();
    agg_kernel<<<(NN * 32 + 255) / 256, 256>>>(x, ea);
    mlp_kernel<<<(NN + 63) / 64, 256, MM_SMEM>>>(b1, b2, x);
    finalize_kernel<<<1, DD>>>(gamma, beta);
    norm_kernel<<<(NN * DD / 4 + 255) / 256, 256>>>(out);
}